// round 1
// baseline (speedup 1.0000x reference)
#include <cuda_runtime.h>
#include <cstdint>
#include <math.h>

// Problem constants
#define BATCH 64
#define QN    2000
#define CN    200
#define NPB   (QN*CN)        // 400000 elements per batch
#define NPB4  (NPB/4)        // 100000 float4 per batch
#define TOPK  100
#define PARTS 9              // chunks per batch -> 64*9 = 576 blocks (~4 waves of 148 SMs)
#define CH4   11112          // ceil(100000/9) float4 per chunk
#define BUF   4096           // per-block candidate buffer (indices)
#define GCAP  (PARTS*BUF)    // per-batch global candidate capacity = 36864
#define NBINS 2048           // histogram bins = top 11 bits of flipped float key
#define FBUF  4096           // final-kernel survivor buffer

// Global scratch (static device arrays: no allocation in kernel_launch)
__device__ float g_cval[(size_t)BATCH * GCAP];
__device__ int   g_cidx[(size_t)BATCH * GCAP];
__device__ int   g_cnt[BATCH];

__device__ __forceinline__ unsigned fkey(float f) {
    unsigned u = __float_as_uint(f);
    return (u & 0x80000000u) ? ~u : (u | 0x80000000u);
}
__device__ __forceinline__ float unkey(unsigned k) {
    unsigned u = (k & 0x80000000u) ? (k ^ 0x80000000u) : ~k;
    return __uint_as_float(u);
}

// Warp-collective (threads 0..31): find max bin g such that
// sum(hist[g..NBINS-1]) >= Keff. Returns (g << 21) on all lanes.
__device__ __forceinline__ unsigned warp_find_thr(const int* hist, int Keff,
                                                  volatile int* sufArr) {
    const int lane = threadIdx.x & 31;
    int part = 0;
#pragma unroll 8
    for (int i = 0; i < 64; i++) part += hist[lane * 64 + i];
    // inclusive suffix scan across lanes (lane l -> sum of bins >= l*64)
    int s = part;
#pragma unroll
    for (int off = 1; off < 32; off <<= 1) {
        int t = __shfl_down_sync(0xFFFFFFFFu, s, off);
        if (lane + off < 32) s += t;
    }
    sufArr[lane] = s;
    __syncwarp();
    unsigned thr = 0;
    if (lane == 0) {
        int c = 0;
        for (int l = 31; l >= 0; l--) {
            if (sufArr[l] >= Keff) { c = l; break; }
        }
        int running = (c < 31) ? sufArr[c + 1] : 0;
        int g = c * 64 + 63;
        for (;; --g) {
            running += hist[g];
            if (running >= Keff || g == c * 64) break;
        }
        thr = ((unsigned)g) << 21;
    }
    thr = __shfl_sync(0xFFFFFFFFu, thr, 0);
    return thr;
}

__global__ void k_zero() {
    int t = threadIdx.x;
    if (t < BATCH) g_cnt[t] = 0;
}

#define PUSH(IDX) do { int _p = atomicAdd(&s_cnt, 1); if (_p < BUF) sidx[_p] = (IDX); } while (0)

__global__ __launch_bounds__(1024)
void k_select(const float* __restrict__ logits) {
    __shared__ int sidx[BUF];
    __shared__ int hist[NBINS];
    __shared__ int sufArr[32];
    __shared__ int s_cnt, s_flag, s_base;
    __shared__ float s_thrF;
    __shared__ unsigned s_thrKey;

    const int tid = threadIdx.x;
    const int blk = blockIdx.x;
    const int b   = blk / PARTS;
    const int prt = blk % PARTS;

    const float4* lp4 = reinterpret_cast<const float4*>(logits) + (size_t)b * NPB4;
    const float*  bb  = logits + (size_t)b * NPB;

    const int base4 = prt * CH4;
    int end4 = base4 + CH4;
    if (end4 > NPB4) end4 = NPB4;

    const float NEG_INF = __int_as_float(0xFF800000);

    for (int i = tid; i < NBINS; i += 1024) hist[i] = 0;
    if (tid == 0) s_cnt = 0;
    __syncthreads();

    // ---- Round 0: first 4096 elements -> histogram -> initial threshold,
    //      then push survivors straight from registers.
    float4 a = __ldg(lp4 + base4 + tid);          // chunk length >= 1024 always
    unsigned kk0 = fkey(a.x), kk1 = fkey(a.y), kk2 = fkey(a.z), kk3 = fkey(a.w);
    atomicAdd(&hist[kk0 >> 21], 1);
    atomicAdd(&hist[kk1 >> 21], 1);
    atomicAdd(&hist[kk2 >> 21], 1);
    atomicAdd(&hist[kk3 >> 21], 1);
    __syncthreads();
    if (tid < 32) {
        unsigned tk = warp_find_thr(hist, TOPK, sufArr);
        if (tid == 0) { s_thrKey = tk; s_thrF = unkey(tk); }
    }
    __syncthreads();
    {
        unsigned tk = s_thrKey;
        int bi = (base4 + tid) * 4;
        if (kk0 >= tk) PUSH(bi);
        if (kk1 >= tk) PUSH(bi + 1);
        if (kk2 >= tk) PUSH(bi + 2);
        if (kk3 >= tk) PUSH(bi + 3);
    }
    __syncthreads();

    // ---- Main rounds: 4 float4 per thread (16384 elems / block / round).
    for (int off = base4 + 1024; off < end4; off += 4096) {
        const float thr = s_thrF;
        const int i0 = off + tid, i1 = i0 + 1024, i2 = i0 + 2048, i3 = i0 + 3072;
        float4 a0 = (i0 < end4) ? __ldg(lp4 + i0) : make_float4(NEG_INF, NEG_INF, NEG_INF, NEG_INF);
        float4 a1 = (i1 < end4) ? __ldg(lp4 + i1) : make_float4(NEG_INF, NEG_INF, NEG_INF, NEG_INF);
        float4 a2 = (i2 < end4) ? __ldg(lp4 + i2) : make_float4(NEG_INF, NEG_INF, NEG_INF, NEG_INF);
        float4 a3 = (i3 < end4) ? __ldg(lp4 + i3) : make_float4(NEG_INF, NEG_INF, NEG_INF, NEG_INF);

        float m0 = fmaxf(fmaxf(a0.x, a0.y), fmaxf(a0.z, a0.w));
        float m1 = fmaxf(fmaxf(a1.x, a1.y), fmaxf(a1.z, a1.w));
        float m2 = fmaxf(fmaxf(a2.x, a2.y), fmaxf(a2.z, a2.w));
        float m3 = fmaxf(fmaxf(a3.x, a3.y), fmaxf(a3.z, a3.w));
        float mm = fmaxf(fmaxf(m0, m1), fmaxf(m2, m3));

        if (mm >= thr) {   // rare path
            if (m0 >= thr) {
                int bi = i0 * 4;
                if (a0.x >= thr) PUSH(bi);
                if (a0.y >= thr) PUSH(bi + 1);
                if (a0.z >= thr) PUSH(bi + 2);
                if (a0.w >= thr) PUSH(bi + 3);
            }
            if (m1 >= thr) {
                int bi = i1 * 4;
                if (a1.x >= thr) PUSH(bi);
                if (a1.y >= thr) PUSH(bi + 1);
                if (a1.z >= thr) PUSH(bi + 2);
                if (a1.w >= thr) PUSH(bi + 3);
            }
            if (m2 >= thr) {
                int bi = i2 * 4;
                if (a2.x >= thr) PUSH(bi);
                if (a2.y >= thr) PUSH(bi + 1);
                if (a2.z >= thr) PUSH(bi + 2);
                if (a2.w >= thr) PUSH(bi + 3);
            }
            if (m3 >= thr) {
                int bi = i3 * 4;
                if (a3.x >= thr) PUSH(bi);
                if (a3.y >= thr) PUSH(bi + 1);
                if (a3.z >= thr) PUSH(bi + 2);
                if (a3.w >= thr) PUSH(bi + 3);
            }
        }
        __syncthreads();
        if (tid == 0) s_flag = (s_cnt > BUF - 2048) ? 1 : 0;
        __syncthreads();
        if (s_flag) {
            // ---- Compaction: rebuild histogram over current candidates,
            //      raise threshold, keep only candidates >= new threshold.
            for (int i = tid; i < NBINS; i += 1024) hist[i] = 0;
            __syncthreads();
            int m = min(s_cnt, BUF);
            for (int j = tid; j < m; j += 1024) {
                float v = __ldg(bb + sidx[j]);
                atomicAdd(&hist[fkey(v) >> 21], 1);
            }
            __syncthreads();
            if (tid < 32) {
                unsigned tk = warp_find_thr(hist, TOPK, sufArr);
                if (tid == 0) { s_thrKey = tk; s_thrF = unkey(tk); }
            }
            __syncthreads();
            unsigned tk = s_thrKey;
            int keep[4]; int nk = 0;
            for (int j = tid; j < m; j += 1024) {
                int id = sidx[j];
                float v = __ldg(bb + id);
                if (fkey(v) >= tk) keep[nk++] = id;
            }
            __syncthreads();
            if (tid == 0) s_cnt = 0;
            __syncthreads();
            if (nk) {
                int p = atomicAdd(&s_cnt, nk);
                for (int q = 0; q < nk; q++)
                    if (p + q < BUF) sidx[p + q] = keep[q];
            }
            __syncthreads();
        }
    }

    // ---- Publish candidates to global per-batch list.
    int wr = min(s_cnt, BUF);
    if (tid == 0) s_base = atomicAdd(&g_cnt[b], wr);
    __syncthreads();
    const size_t gb = (size_t)b * GCAP + s_base;
    for (int j = tid; j < wr; j += 1024) {
        int id = sidx[j];
        g_cidx[gb + j] = id;
        g_cval[gb + j] = __ldg(bb + id);
    }
}

__global__ __launch_bounds__(1024)
void k_final(const float* __restrict__ segs,
             const float* __restrict__ sizes,
             float* __restrict__ out) {
    __shared__ unsigned skey[FBUF];
    __shared__ int sidx2[FBUF];
    __shared__ int hist[NBINS];
    __shared__ int sufArr[32];
    __shared__ int s_cnt;
    __shared__ unsigned s_thrKey;

    const int b = blockIdx.x, tid = threadIdx.x;
    int n = g_cnt[b];
    if (n > GCAP) n = GCAP;
    const float* gv = g_cval + (size_t)b * GCAP;
    const int*   gi = g_cidx + (size_t)b * GCAP;

    for (int i = tid; i < NBINS; i += 1024) hist[i] = 0;
    if (tid == 0) s_cnt = 0;
    __syncthreads();
    for (int j = tid; j < n; j += 1024)
        atomicAdd(&hist[fkey(gv[j]) >> 21], 1);
    __syncthreads();
    const int Keff = (n < TOPK) ? n : TOPK;
    if (tid < 32) {
        unsigned tk = warp_find_thr(hist, Keff, sufArr);
        if (tid == 0) s_thrKey = tk;
    }
    __syncthreads();
    const unsigned tk = s_thrKey;
    for (int j = tid; j < n; j += 1024) {
        unsigned k = fkey(gv[j]);
        if (k >= tk) {
            int p = atomicAdd(&s_cnt, 1);
            if (p < FBUF) { skey[p] = k; sidx2[p] = gi[j]; }
        }
    }
    __syncthreads();
    const int m = min(s_cnt, FBUF);
    const float sz = __ldg(sizes + b);

    // Exact ranking: total order (value desc, index asc) matches jax.lax.top_k.
    for (int i = tid; i < m; i += 1024) {
        const unsigned ki = skey[i];
        const int ii = sidx2[i];
        int rank = 0;
        for (int j = 0; j < m; j++) {
            unsigned kj = skey[j];
            rank += (kj > ki) || (kj == ki && sidx2[j] < ii);
        }
        if (rank < TOPK) {
            float v = unkey(ki);
            float score = 1.0f / (1.0f + expf(-v));
            int q = ii / CN;
            int lab = ii - q * CN;
            float2 seg = reinterpret_cast<const float2*>(segs)[(size_t)b * QN + q];
            float t1 = (seg.x - 0.5f * seg.y) * sz;
            float t2 = (seg.x + 0.5f * seg.y) * sz;
            const int BK = BATCH * TOPK;
            int o = b * TOPK + rank;
            out[o]                 = score;        // scores
            out[BK + o]            = (float)lab;   // labels
            out[2 * BK + 2 * o]     = t1;          // segments[...,0]
            out[2 * BK + 2 * o + 1] = t2;          // segments[...,1]
            out[4 * BK + o]        = (float)q;     // query_ids
        }
    }
}

extern "C" void kernel_launch(void* const* d_in, const int* in_sizes, int n_in,
                              void* d_out, int out_size) {
    const float* logits = (const float*)d_in[0];   // [64,2000,200] f32
    const float* segs   = (const float*)d_in[1];   // [64,2000,2]   f32
    const float* sizes  = (const float*)d_in[2];   // [64]          f32
    float* out = (float*)d_out;

    k_zero<<<1, 64>>>();
    k_select<<<BATCH * PARTS, 1024>>>(logits);
    k_final<<<BATCH, 1024>>>(segs, sizes, out);
}

// round 2
// speedup vs baseline: 1.0014x; 1.0014x over previous
#include <cuda_runtime.h>
#include <cstdint>
#include <math.h>

// Problem constants
#define BATCH 64
#define QN    2000
#define CN    200
#define NPB   (QN*CN)        // 400000 elements per batch
#define NPB4  (NPB/4)        // 100000 float4 per batch
#define TOPK  100
#define PARTS 9              // chunks per batch -> 64*9 = 576 blocks (~4 waves of 148 SMs)
#define CH4   11112          // ceil(100000/9) float4 per chunk
#define BUF   4096           // per-block candidate buffer (indices)
#define GCAP  (PARTS*BUF)    // per-batch global candidate capacity = 36864
#define NBINS 2048           // histogram bins = top 11 bits of flipped float key
#define FBUF  4096           // final-kernel survivor buffer

// Global scratch (static device arrays: no allocation in kernel_launch)
__device__ float g_cval[(size_t)BATCH * GCAP];
__device__ int   g_cidx[(size_t)BATCH * GCAP];
__device__ int   g_cnt[BATCH];

__device__ __forceinline__ unsigned fkey(float f) {
    unsigned u = __float_as_uint(f);
    return (u & 0x80000000u) ? ~u : (u | 0x80000000u);
}
__device__ __forceinline__ float unkey(unsigned k) {
    unsigned u = (k & 0x80000000u) ? (k ^ 0x80000000u) : ~k;
    return __uint_as_float(u);
}

// Warp-collective (threads 0..31): find max bin g such that
// sum(hist[g..NBINS-1]) >= Keff. Returns (g << 21) on all lanes.
__device__ __forceinline__ unsigned warp_find_thr(const int* hist, int Keff,
                                                  volatile int* sufArr) {
    const int lane = threadIdx.x & 31;
    int part = 0;
#pragma unroll 8
    for (int i = 0; i < 64; i++) part += hist[lane * 64 + i];
    // inclusive suffix scan across lanes (lane l -> sum of bins >= l*64)
    int s = part;
#pragma unroll
    for (int off = 1; off < 32; off <<= 1) {
        int t = __shfl_down_sync(0xFFFFFFFFu, s, off);
        if (lane + off < 32) s += t;
    }
    sufArr[lane] = s;
    __syncwarp();
    unsigned thr = 0;
    if (lane == 0) {
        int c = 0;
        for (int l = 31; l >= 0; l--) {
            if (sufArr[l] >= Keff) { c = l; break; }
        }
        int running = (c < 31) ? sufArr[c + 1] : 0;
        int g = c * 64 + 63;
        for (;; --g) {
            running += hist[g];
            if (running >= Keff || g == c * 64) break;
        }
        thr = ((unsigned)g) << 21;
    }
    thr = __shfl_sync(0xFFFFFFFFu, thr, 0);
    return thr;
}

__global__ void k_zero() {
    int t = threadIdx.x;
    if (t < BATCH) g_cnt[t] = 0;
}

#define PUSH(IDX) do { int _p = atomicAdd(&s_cnt, 1); if (_p < BUF) sidx[_p] = (IDX); } while (0)

__global__ __launch_bounds__(1024)
void k_select(const float* __restrict__ logits) {
    __shared__ int sidx[BUF];
    __shared__ int hist[NBINS];
    __shared__ int sufArr[32];
    __shared__ int s_cnt, s_flag, s_base;
    __shared__ float s_thrF;
    __shared__ unsigned s_thrKey;

    const int tid = threadIdx.x;
    const int blk = blockIdx.x;
    const int b   = blk / PARTS;
    const int prt = blk % PARTS;

    const float4* lp4 = reinterpret_cast<const float4*>(logits) + (size_t)b * NPB4;
    const float*  bb  = logits + (size_t)b * NPB;

    const int base4 = prt * CH4;
    int end4 = base4 + CH4;
    if (end4 > NPB4) end4 = NPB4;

    const float NEG_INF = __int_as_float(0xFF800000);

    for (int i = tid; i < NBINS; i += 1024) hist[i] = 0;
    if (tid == 0) s_cnt = 0;
    __syncthreads();

    // ---- Round 0: first 4096 elements -> histogram -> initial threshold,
    //      then push survivors straight from registers.
    float4 a = __ldg(lp4 + base4 + tid);          // chunk length >= 1024 always
    unsigned kk0 = fkey(a.x), kk1 = fkey(a.y), kk2 = fkey(a.z), kk3 = fkey(a.w);
    atomicAdd(&hist[kk0 >> 21], 1);
    atomicAdd(&hist[kk1 >> 21], 1);
    atomicAdd(&hist[kk2 >> 21], 1);
    atomicAdd(&hist[kk3 >> 21], 1);
    __syncthreads();
    if (tid < 32) {
        unsigned tk = warp_find_thr(hist, TOPK, sufArr);
        if (tid == 0) { s_thrKey = tk; s_thrF = unkey(tk); }
    }
    __syncthreads();
    {
        unsigned tk = s_thrKey;
        int bi = (base4 + tid) * 4;
        if (kk0 >= tk) PUSH(bi);
        if (kk1 >= tk) PUSH(bi + 1);
        if (kk2 >= tk) PUSH(bi + 2);
        if (kk3 >= tk) PUSH(bi + 3);
    }
    __syncthreads();

    // ---- Main rounds: 4 float4 per thread (16384 elems / block / round).
    for (int off = base4 + 1024; off < end4; off += 4096) {
        const float thr = s_thrF;
        const int i0 = off + tid, i1 = i0 + 1024, i2 = i0 + 2048, i3 = i0 + 3072;
        float4 a0 = (i0 < end4) ? __ldg(lp4 + i0) : make_float4(NEG_INF, NEG_INF, NEG_INF, NEG_INF);
        float4 a1 = (i1 < end4) ? __ldg(lp4 + i1) : make_float4(NEG_INF, NEG_INF, NEG_INF, NEG_INF);
        float4 a2 = (i2 < end4) ? __ldg(lp4 + i2) : make_float4(NEG_INF, NEG_INF, NEG_INF, NEG_INF);
        float4 a3 = (i3 < end4) ? __ldg(lp4 + i3) : make_float4(NEG_INF, NEG_INF, NEG_INF, NEG_INF);

        float m0 = fmaxf(fmaxf(a0.x, a0.y), fmaxf(a0.z, a0.w));
        float m1 = fmaxf(fmaxf(a1.x, a1.y), fmaxf(a1.z, a1.w));
        float m2 = fmaxf(fmaxf(a2.x, a2.y), fmaxf(a2.z, a2.w));
        float m3 = fmaxf(fmaxf(a3.x, a3.y), fmaxf(a3.z, a3.w));
        float mm = fmaxf(fmaxf(m0, m1), fmaxf(m2, m3));

        if (mm >= thr) {   // rare path
            if (m0 >= thr) {
                int bi = i0 * 4;
                if (a0.x >= thr) PUSH(bi);
                if (a0.y >= thr) PUSH(bi + 1);
                if (a0.z >= thr) PUSH(bi + 2);
                if (a0.w >= thr) PUSH(bi + 3);
            }
            if (m1 >= thr) {
                int bi = i1 * 4;
                if (a1.x >= thr) PUSH(bi);
                if (a1.y >= thr) PUSH(bi + 1);
                if (a1.z >= thr) PUSH(bi + 2);
                if (a1.w >= thr) PUSH(bi + 3);
            }
            if (m2 >= thr) {
                int bi = i2 * 4;
                if (a2.x >= thr) PUSH(bi);
                if (a2.y >= thr) PUSH(bi + 1);
                if (a2.z >= thr) PUSH(bi + 2);
                if (a2.w >= thr) PUSH(bi + 3);
            }
            if (m3 >= thr) {
                int bi = i3 * 4;
                if (a3.x >= thr) PUSH(bi);
                if (a3.y >= thr) PUSH(bi + 1);
                if (a3.z >= thr) PUSH(bi + 2);
                if (a3.w >= thr) PUSH(bi + 3);
            }
        }
        __syncthreads();
        if (tid == 0) s_flag = (s_cnt > BUF - 2048) ? 1 : 0;
        __syncthreads();
        if (s_flag) {
            // ---- Compaction: rebuild histogram over current candidates,
            //      raise threshold, keep only candidates >= new threshold.
            for (int i = tid; i < NBINS; i += 1024) hist[i] = 0;
            __syncthreads();
            int m = min(s_cnt, BUF);
            for (int j = tid; j < m; j += 1024) {
                float v = __ldg(bb + sidx[j]);
                atomicAdd(&hist[fkey(v) >> 21], 1);
            }
            __syncthreads();
            if (tid < 32) {
                unsigned tk = warp_find_thr(hist, TOPK, sufArr);
                if (tid == 0) { s_thrKey = tk; s_thrF = unkey(tk); }
            }
            __syncthreads();
            unsigned tk = s_thrKey;
            int keep[4]; int nk = 0;
            for (int j = tid; j < m; j += 1024) {
                int id = sidx[j];
                float v = __ldg(bb + id);
                if (fkey(v) >= tk) keep[nk++] = id;
            }
            __syncthreads();
            if (tid == 0) s_cnt = 0;
            __syncthreads();
            if (nk) {
                int p = atomicAdd(&s_cnt, nk);
                for (int q = 0; q < nk; q++)
                    if (p + q < BUF) sidx[p + q] = keep[q];
            }
            __syncthreads();
        }
    }

    // ---- Publish candidates to global per-batch list.
    int wr = min(s_cnt, BUF);
    if (tid == 0) s_base = atomicAdd(&g_cnt[b], wr);
    __syncthreads();
    const size_t gb = (size_t)b * GCAP + s_base;
    for (int j = tid; j < wr; j += 1024) {
        int id = sidx[j];
        g_cidx[gb + j] = id;
        g_cval[gb + j] = __ldg(bb + id);
    }
}

__global__ __launch_bounds__(1024)
void k_final(const float* __restrict__ segs,
             const float* __restrict__ sizes,
             float* __restrict__ out) {
    __shared__ unsigned skey[FBUF];
    __shared__ int sidx2[FBUF];
    __shared__ int hist[NBINS];
    __shared__ int sufArr[32];
    __shared__ int s_cnt;
    __shared__ unsigned s_thrKey;

    const int b = blockIdx.x, tid = threadIdx.x;
    int n = g_cnt[b];
    if (n > GCAP) n = GCAP;
    const float* gv = g_cval + (size_t)b * GCAP;
    const int*   gi = g_cidx + (size_t)b * GCAP;

    for (int i = tid; i < NBINS; i += 1024) hist[i] = 0;
    if (tid == 0) s_cnt = 0;
    __syncthreads();
    for (int j = tid; j < n; j += 1024)
        atomicAdd(&hist[fkey(gv[j]) >> 21], 1);
    __syncthreads();
    const int Keff = (n < TOPK) ? n : TOPK;
    if (tid < 32) {
        unsigned tk = warp_find_thr(hist, Keff, sufArr);
        if (tid == 0) s_thrKey = tk;
    }
    __syncthreads();
    const unsigned tk = s_thrKey;
    for (int j = tid; j < n; j += 1024) {
        unsigned k = fkey(gv[j]);
        if (k >= tk) {
            int p = atomicAdd(&s_cnt, 1);
            if (p < FBUF) { skey[p] = k; sidx2[p] = gi[j]; }
        }
    }
    __syncthreads();
    const int m = min(s_cnt, FBUF);
    const float sz = __ldg(sizes + b);

    // Exact ranking: total order (value desc, index asc) matches jax.lax.top_k.
    for (int i = tid; i < m; i += 1024) {
        const unsigned ki = skey[i];
        const int ii = sidx2[i];
        int rank = 0;
        for (int j = 0; j < m; j++) {
            unsigned kj = skey[j];
            rank += (kj > ki) || (kj == ki && sidx2[j] < ii);
        }
        if (rank < TOPK) {
            float v = unkey(ki);
            float score = 1.0f / (1.0f + expf(-v));
            int q = ii / CN;
            int lab = ii - q * CN;
            float2 seg = reinterpret_cast<const float2*>(segs)[(size_t)b * QN + q];
            float t1 = (seg.x - 0.5f * seg.y) * sz;
            float t2 = (seg.x + 0.5f * seg.y) * sz;
            const int BK = BATCH * TOPK;
            int o = b * TOPK + rank;
            out[o]                 = score;        // scores
            out[BK + o]            = (float)lab;   // labels
            out[2 * BK + 2 * o]     = t1;          // segments[...,0]
            out[2 * BK + 2 * o + 1] = t2;          // segments[...,1]
            out[4 * BK + o]        = (float)q;     // query_ids
        }
    }
}

extern "C" void kernel_launch(void* const* d_in, const int* in_sizes, int n_in,
                              void* d_out, int out_size) {
    const float* logits = (const float*)d_in[0];   // [64,2000,200] f32
    const float* segs   = (const float*)d_in[1];   // [64,2000,2]   f32
    const float* sizes  = (const float*)d_in[2];   // [64]          f32
    float* out = (float*)d_out;

    k_zero<<<1, 64>>>();
    k_select<<<BATCH * PARTS, 1024>>>(logits);
    k_final<<<BATCH, 1024>>>(segs, sizes, out);
}